// round 11
// baseline (speedup 1.0000x reference)
#include <cuda_runtime.h>

// Cost volume s2: B=4, C=32, H=W=256, D=9, 8 groups of 4 channels.
// y-offset 0 -> 1D lerp in x; res span 0.8 < 1 px -> 3 taps/side cover all d.
// F folded into the lerp: a = wl-F = (P1-F) + t*S + |t|*Dd.
// Pairwise variance: cost = (1/18) * Sum_ci( a^2 + b^2 - a*b ),  b = wr-F.
// Block = one (b, row h, group PAIR). L/R rows staged in SMEM via coalesced
// float4 __ldcs (single-use, evict-first). F read directly from global
// (coalesced at [w]=tid), issued first to overlap the staging burst.

typedef unsigned long long u64;

constexpr int Wd = 256, Cn = 32, Bn = 4, Dn = 9, Gn = 8, CPG = 4;
constexpr int HW = 256 * 256;
constexpr int RW = 268;          // padded SMEM row: 4 halo + 256 + 8 halo
constexpr int GPB = 2;           // groups per block
constexpr int CB  = GPB * CPG;   // 8 channels staged per block

__device__ __forceinline__ u64 pk(float a, float b) {
    u64 r; asm("mov.b64 %0, {%1, %2};" : "=l"(r) : "f"(a), "f"(b)); return r;
}
__device__ __forceinline__ void upk(float& a, float& b, u64 v) {
    asm("mov.b64 {%0, %1}, %2;" : "=f"(a), "=f"(b) : "l"(v));
}
__device__ __forceinline__ u64 ffma2(u64 a, u64 b, u64 c) {
    u64 d; asm("fma.rn.f32x2 %0, %1, %2, %3;" : "=l"(d) : "l"(a), "l"(b), "l"(c));
    return d;
}
__device__ __forceinline__ u64 add2(u64 a, u64 b) {
    u64 d; asm("add.rn.f32x2 %0, %1, %2;" : "=l"(d) : "l"(a), "l"(b));
    return d;
}

__global__ __launch_bounds__(256, 4) void cost_volume_kernel(
    const float* __restrict__ fref,
    const float* __restrict__ fls,
    const float* __restrict__ frs,
    const float* __restrict__ dinit,
    float* __restrict__ out)
{
    __shared__ float sL[CB][RW];
    __shared__ float sR[CB][RW];

    const int bid = blockIdx.x;          // B*H*(G/2) = 4096 blocks
    const int gp = bid & 3;              // group pair 0..3
    const int h  = (bid >> 2) & 255;
    const int b  = bid >> 10;
    const int tid = threadIdx.x;
    const int w = tid;

    const int rowg0 = b * Cn * HW + gp * CB * HW + h * 256;

    // ---- Direct coalesced loads first: disp + 8 F taps (latency overlaps
    //      the staging burst below) ----
    const float disp = __ldg(dinit + b * HW + h * 256 + w);
    float Fv[CB];
    #pragma unroll
    for (int c8 = 0; c8 < CB; c8++)
        Fv[c8] = __ldcs(fref + rowg0 + c8 * HW + w);

    // ---- Zero halos: 16 rows (8 L + 8 R) x 12 entries ----
    if (tid < 192) {
        const int r   = tid / 12;              // 0..15 : (ci8, arr)
        const int e   = tid % 12;
        const int off = (e < 4) ? e : (256 + e);
        float (*A)[RW] = (r & 1) ? sR : sL;
        A[r >> 1][off] = 0.0f;
    }

    // ---- Stage 16 rows (8ch x {L,R}) as 1024 float4, 4 per thread ----
    #pragma unroll
    for (int k = 0; k < 4; k++) {
        const int j     = tid + (k << 8);
        const int which = j >> 6;              // 0..15
        const int col4  = j & 63;
        const int ci8   = which & 7;
        const float* src = (which & 8) ? frs : fls;
        const float4 v = __ldcs((const float4*)(src + rowg0 + ci8 * HW) + col4);
        if (which & 8) *(float4*)&sR[ci8][4 + (col4 << 2)] = v;
        else           *(float4*)&sL[ci8][4 + (col4 << 2)] = v;
    }

    const float wf = (float)w;

    // Left taps n_l..n_l+2, n_l = floor(x_l at d=0); x_l increases with d.
    const float xl0 = wf + disp - 0.4f;
    const float fll = floorf(xl0);
    const int   n_l = (int)fll;
    const float tl0 = xl0 - fll - 1.0f;
    // Right taps n_r..n_r+2, n_r = floor(x_r at d=8); x_r decreases with d.
    const float xr0 = wf - disp + 0.4f;
    const float flr = floorf(xr0 - 0.8f);
    const int   n_r = (int)flr;
    const float tr0 = xr0 - flr - 1.0f;

    const u64 t02   = pk(tl0, tr0);
    const u64 step2 = pk(0.1f, -0.1f);
    const u64 amask = 0x7FFFFFFF7FFFFFFFull;
    const int il = n_l + 4;
    const int ir = n_r + 4;
    const float c18 = 1.0f / 18.0f;

    __syncthreads();

    float* outbh = out + b * (Gn * Dn * HW) + gp * GPB * Dn * HW + h * 256 + w;

    #pragma unroll
    for (int gg = 0; gg < GPB; gg++) {
        // ---- Gather taps, build packed operands (F pre-subtracted) ----
        u64 P1F[CPG], Sv[CPG], Dd[CPG];
        #pragma unroll
        for (int ci = 0; ci < CPG; ci++) {
            const int c8 = gg * CPG + ci;
            const float L0 = sL[c8][il], L1 = sL[c8][il + 1], L2 = sL[c8][il + 2];
            const float R0 = sR[c8][ir], R1 = sR[c8][ir + 1], R2 = sR[c8][ir + 2];
            const float F  = Fv[c8];

            P1F[ci] = pk(L1 - F, R1 - F);
            Sv[ci]  = pk(0.5f * (L2 - L0), 0.5f * (R2 - R0));
            Dd[ci]  = pk(fmaf(0.5f, L2 + L0, -L1), fmaf(0.5f, R2 + R0, -R1));
        }

        float* outp = outbh + gg * Dn * HW;
        u64 t2 = t02;

        #pragma unroll
        for (int d = 0; d < 9; d++) {
            const u64 at2 = t2 & amask;        // (|t_l|, |t_r|)

            u64 accP = 0ull;
            float ax = 0.0f;
            #pragma unroll
            for (int ci = 0; ci < CPG; ci++) {
                const u64 lw = ffma2(t2, Sv[ci],
                               ffma2(at2, Dd[ci], P1F[ci]));
                accP = ffma2(lw, lw, accP);    // (S a^2, S b^2)
                float a, bb; upk(a, bb, lw);
                ax = fmaf(a, bb, ax);          // S a*b
            }
            t2 = add2(t2, step2);

            float aPl, aPr; upk(aPl, aPr, accP);
            __stcg(outp + d * HW, ((aPl + aPr) - ax) * c18);
        }
    }
}

extern "C" void kernel_launch(void* const* d_in, const int* in_sizes, int n_in,
                              void* d_out, int out_size)
{
    const float* fref  = (const float*)d_in[0];
    const float* fls   = (const float*)d_in[1];
    const float* frs   = (const float*)d_in[2];
    const float* dinit = (const float*)d_in[3];
    float* out = (float*)d_out;

    // blocks over (b, h, group-pair): 4 * 256 * 4 = 4096
    cost_volume_kernel<<<Bn * 256 * (Gn / GPB), 256>>>(fref, fls, frs, dinit, out);
}

// round 13
// speedup vs baseline: 1.0091x; 1.0091x over previous
#include <cuda_runtime.h>

// Cost volume s2: B=4, C=32, H=W=256, D=9, 8 groups of 4 channels.
// y-offset 0 -> 1D lerp in x; res span 0.8 < 1 px -> 3 taps/side cover all d.
// F folded into the lerp: a = wl-F = (P1-F) + t*S + |t|*Dd.
// Pairwise variance: cost = (1/18) * Sum_ci( a^2 + b^2 - a*b ),  b = wr-F.
// Block = one (b, row h, group PAIR). L/R rows staged in SMEM via coalesced
// float4 __ldg; F read directly from global with plain __ldg (coalesced at
// [w]=tid), issued before the staging burst so its latency overlaps it.
// (R11 showed __ldcs evict-first hints thrash L2 on this pattern: avoided.)

typedef unsigned long long u64;

constexpr int Wd = 256, Cn = 32, Bn = 4, Dn = 9, Gn = 8, CPG = 4;
constexpr int HW = 256 * 256;
constexpr int RW = 268;          // padded SMEM row: 4 halo + 256 + 8 halo
constexpr int GPB = 2;           // groups per block
constexpr int CB  = GPB * CPG;   // 8 channels staged per block

__device__ __forceinline__ u64 pk(float a, float b) {
    u64 r; asm("mov.b64 %0, {%1, %2};" : "=l"(r) : "f"(a), "f"(b)); return r;
}
__device__ __forceinline__ void upk(float& a, float& b, u64 v) {
    asm("mov.b64 {%0, %1}, %2;" : "=f"(a), "=f"(b) : "l"(v));
}
__device__ __forceinline__ u64 ffma2(u64 a, u64 b, u64 c) {
    u64 d; asm("fma.rn.f32x2 %0, %1, %2, %3;" : "=l"(d) : "l"(a), "l"(b), "l"(c));
    return d;
}
__device__ __forceinline__ u64 add2(u64 a, u64 b) {
    u64 d; asm("add.rn.f32x2 %0, %1, %2;" : "=l"(d) : "l"(a), "l"(b));
    return d;
}

__global__ __launch_bounds__(256, 4) void cost_volume_kernel(
    const float* __restrict__ fref,
    const float* __restrict__ fls,
    const float* __restrict__ frs,
    const float* __restrict__ dinit,
    float* __restrict__ out)
{
    __shared__ float sL[CB][RW];
    __shared__ float sR[CB][RW];

    const int bid = blockIdx.x;          // B*H*(G/2) = 4096 blocks
    const int gp = bid & 3;              // group pair 0..3
    const int h  = (bid >> 2) & 255;
    const int b  = bid >> 10;
    const int tid = threadIdx.x;
    const int w = tid;

    const int rowg0 = b * Cn * HW + gp * CB * HW + h * 256;

    // ---- Direct coalesced loads first: disp + 8 F taps (their DRAM latency
    //      overlaps the staging burst below) ----
    const float disp = __ldg(dinit + b * HW + h * 256 + w);
    float Fv[CB];
    #pragma unroll
    for (int c8 = 0; c8 < CB; c8++)
        Fv[c8] = __ldg(fref + rowg0 + c8 * HW + w);

    // ---- Zero halos: 16 rows (8 L + 8 R) x 12 entries ----
    if (tid < 192) {
        const int r   = tid / 12;              // 0..15 : (ci8, arr)
        const int e   = tid % 12;
        const int off = (e < 4) ? e : (256 + e);
        float (*A)[RW] = (r & 1) ? sR : sL;
        A[r >> 1][off] = 0.0f;
    }

    // ---- Stage 16 rows (8ch x {L,R}) as 1024 float4, 4 per thread ----
    #pragma unroll
    for (int k = 0; k < 4; k++) {
        const int j     = tid + (k << 8);
        const int which = j >> 6;              // 0..15
        const int col4  = j & 63;
        const int ci8   = which & 7;
        const float* src = (which & 8) ? frs : fls;
        const float4 v = __ldg((const float4*)(src + rowg0 + ci8 * HW) + col4);
        if (which & 8) *(float4*)&sR[ci8][4 + (col4 << 2)] = v;
        else           *(float4*)&sL[ci8][4 + (col4 << 2)] = v;
    }

    const float wf = (float)w;

    // Left taps n_l..n_l+2, n_l = floor(x_l at d=0); x_l increases with d.
    const float xl0 = wf + disp - 0.4f;
    const float fll = floorf(xl0);
    const int   n_l = (int)fll;
    const float tl0 = xl0 - fll - 1.0f;
    // Right taps n_r..n_r+2, n_r = floor(x_r at d=8); x_r decreases with d.
    const float xr0 = wf - disp + 0.4f;
    const float flr = floorf(xr0 - 0.8f);
    const int   n_r = (int)flr;
    const float tr0 = xr0 - flr - 1.0f;

    const u64 t02   = pk(tl0, tr0);
    const u64 step2 = pk(0.1f, -0.1f);
    const u64 amask = 0x7FFFFFFF7FFFFFFFull;
    const int il = n_l + 4;
    const int ir = n_r + 4;
    const float c18 = 1.0f / 18.0f;

    __syncthreads();

    float* outbh = out + b * (Gn * Dn * HW) + gp * GPB * Dn * HW + h * 256 + w;

    #pragma unroll
    for (int gg = 0; gg < GPB; gg++) {
        // ---- Gather taps, build packed operands (F pre-subtracted) ----
        u64 P1F[CPG], Sv[CPG], Dd[CPG];
        #pragma unroll
        for (int ci = 0; ci < CPG; ci++) {
            const int c8 = gg * CPG + ci;
            const float L0 = sL[c8][il], L1 = sL[c8][il + 1], L2 = sL[c8][il + 2];
            const float R0 = sR[c8][ir], R1 = sR[c8][ir + 1], R2 = sR[c8][ir + 2];
            const float F  = Fv[c8];

            P1F[ci] = pk(L1 - F, R1 - F);
            Sv[ci]  = pk(0.5f * (L2 - L0), 0.5f * (R2 - R0));
            Dd[ci]  = pk(fmaf(0.5f, L2 + L0, -L1), fmaf(0.5f, R2 + R0, -R1));
        }

        float* outp = outbh + gg * Dn * HW;
        u64 t2 = t02;

        #pragma unroll
        for (int d = 0; d < 9; d++) {
            const u64 at2 = t2 & amask;        // (|t_l|, |t_r|)

            u64 accP = 0ull;
            float ax = 0.0f;
            #pragma unroll
            for (int ci = 0; ci < CPG; ci++) {
                const u64 lw = ffma2(t2, Sv[ci],
                               ffma2(at2, Dd[ci], P1F[ci]));
                accP = ffma2(lw, lw, accP);    // (S a^2, S b^2)
                float a, bb; upk(a, bb, lw);
                ax = fmaf(a, bb, ax);          // S a*b
            }
            t2 = add2(t2, step2);

            float aPl, aPr; upk(aPl, aPr, accP);
            __stcg(outp + d * HW, ((aPl + aPr) - ax) * c18);
        }
    }
}

extern "C" void kernel_launch(void* const* d_in, const int* in_sizes, int n_in,
                              void* d_out, int out_size)
{
    const float* fref  = (const float*)d_in[0];
    const float* fls   = (const float*)d_in[1];
    const float* frs   = (const float*)d_in[2];
    const float* dinit = (const float*)d_in[3];
    float* out = (float*)d_out;

    // blocks over (b, h, group-pair): 4 * 256 * 4 = 4096
    cost_volume_kernel<<<Bn * 256 * (Gn / GPB), 256>>>(fref, fls, frs, dinit, out);
}

// round 14
// speedup vs baseline: 1.0907x; 1.0809x over previous
#include <cuda_runtime.h>

// Cost volume s2: B=4, C=32, H=W=256, D=9, 8 groups of 4 channels.
// y-offset 0 -> 1D lerp in x; res span 0.8 < 1 px -> 3 taps/side cover all d.
// F folded into the lerp: a = wl-F = (P1-F) + t*S + |t|*Dd.
// Pairwise variance: cost = (1/18) * Sum_ci( a^2 + b^2 - a*b ),  b = wr-F.
// Block = one (b, row h, group PAIR). Rows staged into SMEM by cp.async.bulk
// (UBLKCP, async engine) + mbarrier -- zero warp-issued staging LDG/STS, so
// the L1tex wavefront queue (the measured binder R10-R13) stays empty.
// Taps gathered via LDS; zero halo = zero padding (no predicates).

typedef unsigned long long u64;

constexpr int Wd = 256, Cn = 32, Bn = 4, Dn = 9, Gn = 8, CPG = 4;
constexpr int HW = 256 * 256;
constexpr int RW = 268;          // padded SMEM row: 4 halo + 256 + 8 halo
constexpr int GPB = 2;           // groups per block
constexpr int CB  = GPB * CPG;   // 8 channels staged per block

__device__ __forceinline__ u64 pk(float a, float b) {
    u64 r; asm("mov.b64 %0, {%1, %2};" : "=l"(r) : "f"(a), "f"(b)); return r;
}
__device__ __forceinline__ void upk(float& a, float& b, u64 v) {
    asm("mov.b64 {%0, %1}, %2;" : "=f"(a), "=f"(b) : "l"(v));
}
__device__ __forceinline__ u64 ffma2(u64 a, u64 b, u64 c) {
    u64 d; asm("fma.rn.f32x2 %0, %1, %2, %3;" : "=l"(d) : "l"(a), "l"(b), "l"(c));
    return d;
}
__device__ __forceinline__ u64 add2(u64 a, u64 b) {
    u64 d; asm("add.rn.f32x2 %0, %1, %2;" : "=l"(d) : "l"(a), "l"(b));
    return d;
}
__device__ __forceinline__ unsigned su(const void* p) {
    return (unsigned)__cvta_generic_to_shared(p);
}
__device__ __forceinline__ void bulk_g2s(unsigned dst, const void* src,
                                         unsigned bytes, unsigned mbar) {
    asm volatile(
        "cp.async.bulk.shared::cluster.global.mbarrier::complete_tx::bytes "
        "[%0], [%1], %2, [%3];"
        :: "r"(dst), "l"(src), "r"(bytes), "r"(mbar) : "memory");
}

__global__ __launch_bounds__(256, 4) void cost_volume_kernel(
    const float* __restrict__ fref,
    const float* __restrict__ fls,
    const float* __restrict__ frs,
    const float* __restrict__ dinit,
    float* __restrict__ out)
{
    __shared__ float sL[CB][RW];
    __shared__ float sR[CB][RW];
    __shared__ float sF[CB][256];
    __shared__ __align__(8) u64 mbar;

    const int bid = blockIdx.x;          // B*H*(G/2) = 4096 blocks
    const int gp = bid & 3;              // group pair 0..3
    const int h  = (bid >> 2) & 255;
    const int b  = bid >> 10;
    const int tid = threadIdx.x;
    const int w = tid;

    const unsigned mb = su(&mbar);

    if (tid == 0) {
        asm volatile("mbarrier.init.shared.b64 [%0], %1;" :: "r"(mb), "r"(1)
                     : "memory");
    }
    __syncthreads();   // init visible before any arrive/tx

    const int rowg0 = b * Cn * HW + gp * CB * HW + h * 256;

    if (tid == 0) {
        asm volatile("mbarrier.arrive.expect_tx.shared.b64 _, [%0], %1;"
                     :: "r"(mb), "r"(24u * 1024u) : "memory");
        #pragma unroll
        for (int ci = 0; ci < CB; ci++) {
            const int rb = rowg0 + ci * HW;
            bulk_g2s(su(&sL[ci][4]), fls  + rb, 1024u, mb);
            bulk_g2s(su(&sR[ci][4]), frs  + rb, 1024u, mb);
            bulk_g2s(su(&sF[ci][0]), fref + rb, 1024u, mb);
        }
    }

    // ---- Zero halos: 16 rows (8 L + 8 R) x 12 entries (disjoint from TMA) ----
    if (tid < 192) {
        const int r   = tid / 12;              // 0..15 : (ci8, arr)
        const int e   = tid % 12;
        const int off = (e < 4) ? e : (256 + e);
        float (*A)[RW] = (r & 1) ? sR : sL;
        A[r >> 1][off] = 0.0f;
    }

    // ---- Head math (overlaps the bulk copies) ----
    const float disp = __ldg(dinit + b * HW + h * 256 + w);
    const float wf = (float)w;

    // Left taps n_l..n_l+2, n_l = floor(x_l at d=0); x_l increases with d.
    const float xl0 = wf + disp - 0.4f;
    const float fll = floorf(xl0);
    const int   n_l = (int)fll;
    const float tl0 = xl0 - fll - 1.0f;
    // Right taps n_r..n_r+2, n_r = floor(x_r at d=8); x_r decreases with d.
    const float xr0 = wf - disp + 0.4f;
    const float flr = floorf(xr0 - 0.8f);
    const int   n_r = (int)flr;
    const float tr0 = xr0 - flr - 1.0f;

    const u64 t02   = pk(tl0, tr0);
    const u64 step2 = pk(0.1f, -0.1f);
    const u64 amask = 0x7FFFFFFF7FFFFFFFull;
    const int il = n_l + 4;
    const int ir = n_r + 4;
    const float c18 = 1.0f / 18.0f;

    __syncthreads();   // halo STS visible to all threads

    // Wait for the 24 KB of bulk copies (phase 0).
    {
        unsigned done;
        asm volatile(
            "{\n\t.reg .pred p;\n\t"
            "mbarrier.try_wait.parity.acquire.cta.shared::cta.b64 p, [%1], 0;\n\t"
            "selp.b32 %0, 1, 0, p;\n\t}"
            : "=r"(done) : "r"(mb) : "memory");
        if (!done) {
            asm volatile(
                "{\n\t.reg .pred P1;\n\t"
                "WAIT_LOOP:\n\t"
                "mbarrier.try_wait.parity.acquire.cta.shared::cta.b64 P1, [%0], 0, 0x989680;\n\t"
                "@P1 bra.uni WAIT_DONE;\n\t"
                "bra.uni WAIT_LOOP;\n\t"
                "WAIT_DONE:\n\t}"
                :: "r"(mb) : "memory");
        }
    }

    float* outbh = out + b * (Gn * Dn * HW) + gp * GPB * Dn * HW + h * 256 + w;

    #pragma unroll
    for (int gg = 0; gg < GPB; gg++) {
        // ---- Gather taps, build packed operands (F pre-subtracted) ----
        u64 P1F[CPG], Sv[CPG], Dd[CPG];
        #pragma unroll
        for (int ci = 0; ci < CPG; ci++) {
            const int c8 = gg * CPG + ci;
            const float L0 = sL[c8][il], L1 = sL[c8][il + 1], L2 = sL[c8][il + 2];
            const float R0 = sR[c8][ir], R1 = sR[c8][ir + 1], R2 = sR[c8][ir + 2];
            const float F  = sF[c8][w];

            P1F[ci] = pk(L1 - F, R1 - F);
            Sv[ci]  = pk(0.5f * (L2 - L0), 0.5f * (R2 - R0));
            Dd[ci]  = pk(fmaf(0.5f, L2 + L0, -L1), fmaf(0.5f, R2 + R0, -R1));
        }

        float* outp = outbh + gg * Dn * HW;
        u64 t2 = t02;

        #pragma unroll
        for (int d = 0; d < 9; d++) {
            const u64 at2 = t2 & amask;        // (|t_l|, |t_r|)

            u64 accP = 0ull;
            float ax = 0.0f;
            #pragma unroll
            for (int ci = 0; ci < CPG; ci++) {
                const u64 lw = ffma2(t2, Sv[ci],
                               ffma2(at2, Dd[ci], P1F[ci]));
                accP = ffma2(lw, lw, accP);    // (S a^2, S b^2)
                float a, bb; upk(a, bb, lw);
                ax = fmaf(a, bb, ax);          // S a*b
            }
            t2 = add2(t2, step2);

            float aPl, aPr; upk(aPl, aPr, accP);
            __stcg(outp + d * HW, ((aPl + aPr) - ax) * c18);
        }
    }
}

extern "C" void kernel_launch(void* const* d_in, const int* in_sizes, int n_in,
                              void* d_out, int out_size)
{
    const float* fref  = (const float*)d_in[0];
    const float* fls   = (const float*)d_in[1];
    const float* frs   = (const float*)d_in[2];
    const float* dinit = (const float*)d_in[3];
    float* out = (float*)d_out;

    // blocks over (b, h, group-pair): 4 * 256 * 4 = 4096
    cost_volume_kernel<<<Bn * 256 * (Gn / GPB), 256>>>(fref, fls, frs, dinit, out);
}

// round 15
// speedup vs baseline: 1.3200x; 1.2102x over previous
#include <cuda_runtime.h>

// Cost volume s2: B=4, C=32, H=W=256, D=9, 8 groups of 4 channels.
// y-offset 0 -> 1D lerp in x; res span 0.8 < 1 px -> 3 taps/side cover all d.
// F folded into the lerp: a = wl-F = (P1-F) + t*S + |t|*Dd  (S=(P2-P0)/2,
// Dd=(P2+P0)/2-P1).  Pairwise variance:
//   cost = (1/18) * Sum_ci( a^2 + b^2 - a*b ),  b = wr-F.
// Inner body: 4 issue slots per (d,channel), 3 of them packed f32x2 (FFMA2).
// Block = one (b, row h, group PAIR): rows staged in SMEM via coalesced
// float4 loads; taps gathered via conflict-free LDS; zero halo = zero
// padding (no validity predicates).
//
// Bracketed-optimal configuration (R7-R14 experiments):
//   groups/block = 2 (1 and 4 both slower), no reg ceiling (forced 51-reg cap
//   regressed), no cache hints on loads (__ldcs regressed), F staged through
//   SMEM (direct-LDG regressed), LDG.128 staging (TMA bulk regressed),
//   front-batched LDG per thread kept <= 6 (L1tex-queue contention law).

typedef unsigned long long u64;

constexpr int Wd = 256, Cn = 32, Bn = 4, Dn = 9, Gn = 8, CPG = 4;
constexpr int HW = 256 * 256;
constexpr int RW = 268;          // padded SMEM row: 4 halo + 256 + 8 halo
constexpr int GPB = 2;           // groups per block
constexpr int CB  = GPB * CPG;   // 8 channels staged per block

__device__ __forceinline__ u64 pk(float a, float b) {
    u64 r; asm("mov.b64 %0, {%1, %2};" : "=l"(r) : "f"(a), "f"(b)); return r;
}
__device__ __forceinline__ void upk(float& a, float& b, u64 v) {
    asm("mov.b64 {%0, %1}, %2;" : "=f"(a), "=f"(b) : "l"(v));
}
__device__ __forceinline__ u64 ffma2(u64 a, u64 b, u64 c) {
    u64 d; asm("fma.rn.f32x2 %0, %1, %2, %3;" : "=l"(d) : "l"(a), "l"(b), "l"(c));
    return d;
}
__device__ __forceinline__ u64 add2(u64 a, u64 b) {
    u64 d; asm("add.rn.f32x2 %0, %1, %2;" : "=l"(d) : "l"(a), "l"(b));
    return d;
}

__global__ __launch_bounds__(256, 4) void cost_volume_kernel(
    const float* __restrict__ fref,
    const float* __restrict__ fls,
    const float* __restrict__ frs,
    const float* __restrict__ dinit,
    float* __restrict__ out)
{
    __shared__ float sL[CB][RW];
    __shared__ float sR[CB][RW];
    __shared__ float sF[CB][256];

    const int bid = blockIdx.x;          // B*H*(G/2) = 4096 blocks
    const int gp = bid & 3;              // group pair 0..3
    const int h  = (bid >> 2) & 255;
    const int b  = bid >> 10;
    const int tid = threadIdx.x;
    const int w = tid;

    // ---- Zero halos: 16 rows (8 L + 8 R) x 12 entries ----
    if (tid < 192) {
        const int r   = tid / 12;              // 0..15 : (ci8, arr)
        const int e   = tid % 12;
        const int off = (e < 4) ? e : (256 + e);
        float (*A)[RW] = (r & 1) ? sR : sL;
        A[r >> 1][off] = 0.0f;
    }

    // ---- Stage 24 rows (8ch x {L,R,F}) as 1536 float4, 6 per thread ----
    {
        const int rowg0 = b * Cn * HW + gp * CB * HW + h * 256;
        #pragma unroll
        for (int k = 0; k < 6; k++) {
            const int j     = tid + (k << 8);
            const int which = j >> 6;          // 0..23
            const int col4  = j & 63;
            const int ci8   = which & 7;
            const int arr   = which >> 3;      // 0=L 1=R 2=F
            const float* src = (arr == 0) ? fls : (arr == 1) ? frs : fref;
            const float4 v = __ldg((const float4*)(src + rowg0 + ci8 * HW) + col4);
            if (arr == 0)      *(float4*)&sL[ci8][4 + (col4 << 2)] = v;
            else if (arr == 1) *(float4*)&sR[ci8][4 + (col4 << 2)] = v;
            else               *(float4*)&sF[ci8][col4 << 2] = v;
        }
    }

    const float disp = __ldg(dinit + b * HW + h * 256 + w);
    const float wf = (float)w;

    // Left taps n_l..n_l+2, n_l = floor(x_l at d=0); x_l increases with d.
    const float xl0 = wf + disp - 0.4f;
    const float fll = floorf(xl0);
    const int   n_l = (int)fll;
    const float tl0 = xl0 - fll - 1.0f;
    // Right taps n_r..n_r+2, n_r = floor(x_r at d=8); x_r decreases with d.
    const float xr0 = wf - disp + 0.4f;
    const float flr = floorf(xr0 - 0.8f);
    const int   n_r = (int)flr;
    const float tr0 = xr0 - flr - 1.0f;

    const u64 t02   = pk(tl0, tr0);
    const u64 step2 = pk(0.1f, -0.1f);
    const u64 amask = 0x7FFFFFFF7FFFFFFFull;
    const int il = n_l + 4;
    const int ir = n_r + 4;
    const float c18 = 1.0f / 18.0f;

    __syncthreads();

    float* outbh = out + b * (Gn * Dn * HW) + gp * GPB * Dn * HW + h * 256 + w;

    #pragma unroll
    for (int gg = 0; gg < GPB; gg++) {
        // ---- Gather taps, build packed operands (F pre-subtracted) ----
        u64 P1F[CPG], Sv[CPG], Dd[CPG];
        #pragma unroll
        for (int ci = 0; ci < CPG; ci++) {
            const int c8 = gg * CPG + ci;
            const float L0 = sL[c8][il], L1 = sL[c8][il + 1], L2 = sL[c8][il + 2];
            const float R0 = sR[c8][ir], R1 = sR[c8][ir + 1], R2 = sR[c8][ir + 2];
            const float F  = sF[c8][w];

            P1F[ci] = pk(L1 - F, R1 - F);
            Sv[ci]  = pk(0.5f * (L2 - L0), 0.5f * (R2 - R0));
            Dd[ci]  = pk(fmaf(0.5f, L2 + L0, -L1), fmaf(0.5f, R2 + R0, -R1));
        }

        float* outp = outbh + gg * Dn * HW;
        u64 t2 = t02;

        #pragma unroll
        for (int d = 0; d < 9; d++) {
            const u64 at2 = t2 & amask;        // (|t_l|, |t_r|)

            u64 accP = 0ull;
            float ax = 0.0f;
            #pragma unroll
            for (int ci = 0; ci < CPG; ci++) {
                const u64 lw = ffma2(t2, Sv[ci],
                               ffma2(at2, Dd[ci], P1F[ci]));
                accP = ffma2(lw, lw, accP);    // (S a^2, S b^2)
                float a, bb; upk(a, bb, lw);
                ax = fmaf(a, bb, ax);          // S a*b
            }
            t2 = add2(t2, step2);

            float aPl, aPr; upk(aPl, aPr, accP);
            __stcg(outp + d * HW, ((aPl + aPr) - ax) * c18);
        }
    }
}

extern "C" void kernel_launch(void* const* d_in, const int* in_sizes, int n_in,
                              void* d_out, int out_size)
{
    const float* fref  = (const float*)d_in[0];
    const float* fls   = (const float*)d_in[1];
    const float* frs   = (const float*)d_in[2];
    const float* dinit = (const float*)d_in[3];
    float* out = (float*)d_out;

    // blocks over (b, h, group-pair): 4 * 256 * 4 = 4096
    cost_volume_kernel<<<Bn * 256 * (Gn / GPB), 256>>>(fref, fls, frs, dinit, out);
}